// round 2
// baseline (speedup 1.0000x reference)
#include <cuda_runtime.h>
#include <math.h>

#define B_    2
#define S_    2048
#define HID_  2048
#define NH_   16
#define HS_   128
#define QKV3  6144   // 3*HID
#define HEAD3 384    // 3*HS

// Scratch (device globals — no allocation allowed)
__device__ float g_qkv[(size_t)B_ * S_ * QKV3];   // ~100 MB
__device__ float g_attn[(size_t)B_ * S_ * HID_];  // ~33 MB

// ---------------------------------------------------------------------------
// SGEMM: C[M,N] = A[M,K] @ W[K,N] + bias[N]   (row-major, 128x128x8 tiles)
// 256 threads, each computes 8x8 in split layout (rows ty*4 & 64+ty*4, cols
// tx*4 & 64+tx*4) for conflict-free float4 LDS.
// ---------------------------------------------------------------------------
__global__ __launch_bounds__(256, 2)
void sgemm_bias(const float* __restrict__ A, const float* __restrict__ W,
                const float* __restrict__ bias, float* __restrict__ C,
                int M, int N, int K)
{
    __shared__ float As[8][128];
    __shared__ float Bs[8][128];

    const int tid = threadIdx.x;
    const int bm = blockIdx.y * 128;
    const int bn = blockIdx.x * 128;
    const int ty = tid >> 4;      // 0..15
    const int tx = tid & 15;      // 0..15

    float acc[8][8];
#pragma unroll
    for (int i = 0; i < 8; i++)
#pragma unroll
        for (int j = 0; j < 8; j++) acc[i][j] = 0.f;

    const int arow = tid >> 1;            // 0..127
    const int acol = (tid & 1) << 2;      // 0 or 4
    const int brow = tid >> 5;            // 0..7
    const int bcol = (tid & 31) << 2;     // 0..124

    const float* Aptr = A + (size_t)(bm + arow) * K + acol;
    const float* Wptr = W + (size_t)brow * N + bn + bcol;

    for (int k0 = 0; k0 < K; k0 += 8) {
        float4 av = *(const float4*)(Aptr + k0);
        As[acol + 0][arow] = av.x;
        As[acol + 1][arow] = av.y;
        As[acol + 2][arow] = av.z;
        As[acol + 3][arow] = av.w;
        float4 bv = *(const float4*)(Wptr + (size_t)k0 * N);
        *(float4*)&Bs[brow][bcol] = bv;
        __syncthreads();

#pragma unroll
        for (int k = 0; k < 8; k++) {
            float ra[8], rb[8];
            *(float4*)&ra[0] = *(float4*)&As[k][ty * 4];
            *(float4*)&ra[4] = *(float4*)&As[k][64 + ty * 4];
            *(float4*)&rb[0] = *(float4*)&Bs[k][tx * 4];
            *(float4*)&rb[4] = *(float4*)&Bs[k][64 + tx * 4];
#pragma unroll
            for (int i = 0; i < 8; i++)
#pragma unroll
                for (int j = 0; j < 8; j++)
                    acc[i][j] += ra[i] * rb[j];
        }
        __syncthreads();
    }

#pragma unroll
    for (int ih = 0; ih < 2; ih++)
#pragma unroll
        for (int i = 0; i < 4; i++) {
            int row = bm + ih * 64 + ty * 4 + i;
#pragma unroll
            for (int jh = 0; jh < 2; jh++) {
                int col = bn + jh * 64 + tx * 4;
                float4 v;
                v.x = acc[ih * 4 + i][jh * 4 + 0] + bias[col + 0];
                v.y = acc[ih * 4 + i][jh * 4 + 1] + bias[col + 1];
                v.z = acc[ih * 4 + i][jh * 4 + 2] + bias[col + 2];
                v.w = acc[ih * 4 + i][jh * 4 + 3] + bias[col + 3];
                *(float4*)(C + (size_t)row * N + col) = v;
            }
        }
}

// ---------------------------------------------------------------------------
// RoPE in place on q and k (first ROT=32 dims, half=16), positions = s.
// one thread per (b,s,h,d<16)
// ---------------------------------------------------------------------------
__global__ void rope_kernel()
{
    int idx = blockIdx.x * blockDim.x + threadIdx.x;
    // total = B*S*NH*16
    int d = idx & 15;
    int h = (idx >> 4) & (NH_ - 1);
    int s = (idx >> 8) & (S_ - 1);
    int b = idx >> 19;
    if (b >= B_) return;

    float inv = powf(10000.f, -((float)(2 * d) / 32.f));
    float ang = (float)s * inv;
    float c = cosf(ang);
    float sn = sinf(ang);

    float* base = g_qkv + ((size_t)(b * S_ + s)) * QKV3 + h * HEAD3;
    // q
    float x1 = base[d], x2 = base[d + 16];
    base[d]      = x1 * c - x2 * sn;
    base[d + 16] = x2 * c + x1 * sn;
    // k
    x1 = base[HS_ + d]; x2 = base[HS_ + d + 16];
    base[HS_ + d]      = x1 * c - x2 * sn;
    base[HS_ + d + 16] = x2 * c + x1 * sn;
}

// ---------------------------------------------------------------------------
// Flash attention (fp32, causal). BM=BKV=64, 256 threads.
// Thread t: row r=t>>2, quad lane q4=t&3.
//   S-cols: c = i*4+q4 (i<16);  O float4-chunks: d4 = q4+4*j4 (j4<8)
// Padded smem strides avoid bank conflicts.
// ---------------------------------------------------------------------------
#define RS 132   // row stride (floats) for Q/K/V tiles
#define PS 65    // row stride for P tile
#define ATTN_SMEM ((3 * 64 * RS + 64 * PS) * 4)

__global__ __launch_bounds__(256)
void attn_kernel()
{
    extern __shared__ float sm[];
    float* Qs = sm;                    // 64*RS
    float* Ks = Qs + 64 * RS;
    float* Vs = Ks + 64 * RS;
    float* Ps = Vs + 64 * RS;          // 64*PS

    const int b = blockIdx.z, h = blockIdx.y, qt = blockIdx.x;
    const int tid = threadIdx.x;
    const int r = tid >> 2;
    const int q4 = tid & 3;
    const float scale = 0.08838834764831845f;  // 1/sqrt(128)

    const size_t qkvbase = (size_t)b * S_ * QKV3 + (size_t)h * HEAD3;

    // load Q tile (rows qt*64 .. +63, 128 floats each)
    for (int e = tid; e < 64 * 32; e += 256) {
        int row = e >> 5, c4 = e & 31;
        float4 v = *(const float4*)(g_qkv + qkvbase + (size_t)(qt * 64 + row) * QKV3 + c4 * 4);
        *(float4*)&Qs[row * RS + c4 * 4] = v;
    }

    float o[32];
#pragma unroll
    for (int i = 0; i < 32; i++) o[i] = 0.f;
    float m_i = -1e30f, l_i = 0.f;

    const int rg = qt * 64 + r;
    const int ntiles = qt + 1;

    for (int kt = 0; kt < ntiles; kt++) {
        __syncthreads();
        // load K and V tiles
        for (int e = tid; e < 64 * 32; e += 256) {
            int row = e >> 5, c4 = e & 31;
            const float* g = g_qkv + qkvbase + (size_t)(kt * 64 + row) * QKV3 + c4 * 4;
            *(float4*)&Ks[row * RS + c4 * 4] = *(const float4*)(g + HS_);
            *(float4*)&Vs[row * RS + c4 * 4] = *(const float4*)(g + 2 * HS_);
        }
        __syncthreads();

        // S = Q K^T for this thread's 16 columns
        float sacc[16];
#pragma unroll
        for (int i = 0; i < 16; i++) sacc[i] = 0.f;
#pragma unroll 4
        for (int d4 = 0; d4 < 32; d4++) {
            float4 qv = *(float4*)&Qs[r * RS + d4 * 4];
#pragma unroll
            for (int i = 0; i < 16; i++) {
                int c = i * 4 + q4;
                float4 kv = *(float4*)&Ks[c * RS + d4 * 4];
                sacc[i] += qv.x * kv.x + qv.y * kv.y + qv.z * kv.z + qv.w * kv.w;
            }
        }

        // scale + causal mask
#pragma unroll
        for (int i = 0; i < 16; i++) {
            int cg = kt * 64 + i * 4 + q4;
            sacc[i] = (cg <= rg) ? sacc[i] * scale : -1e30f;
        }

        // online softmax (quad reduction: lanes r*4+q4 are consecutive)
        float tmax = sacc[0];
#pragma unroll
        for (int i = 1; i < 16; i++) tmax = fmaxf(tmax, sacc[i]);
        tmax = fmaxf(tmax, __shfl_xor_sync(0xffffffffu, tmax, 1));
        tmax = fmaxf(tmax, __shfl_xor_sync(0xffffffffu, tmax, 2));
        float m_new = fmaxf(m_i, tmax);
        float alpha = expf(m_i - m_new);

        float p[16];
        float psum = 0.f;
#pragma unroll
        for (int i = 0; i < 16; i++) {
            p[i] = expf(sacc[i] - m_new);
            psum += p[i];
        }
        psum += __shfl_xor_sync(0xffffffffu, psum, 1);
        psum += __shfl_xor_sync(0xffffffffu, psum, 2);

        l_i = l_i * alpha + psum;
        m_i = m_new;
#pragma unroll
        for (int j = 0; j < 32; j++) o[j] *= alpha;

#pragma unroll
        for (int i = 0; i < 16; i++) Ps[r * PS + i * 4 + q4] = p[i];
        __syncthreads();

        // O += P @ V  (thread owns float4 chunks d4 = q4 + 4*j4)
        for (int c = 0; c < 64; c++) {
            float pr = Ps[r * PS + c];
#pragma unroll
            for (int j4 = 0; j4 < 8; j4++) {
                float4 vv = *(float4*)&Vs[c * RS + (q4 + 4 * j4) * 4];
                o[j4 * 4 + 0] += pr * vv.x;
                o[j4 * 4 + 1] += pr * vv.y;
                o[j4 * 4 + 2] += pr * vv.z;
                o[j4 * 4 + 3] += pr * vv.w;
            }
        }
    }

    // epilogue: normalize, write to g_attn [B,S,HID]
    float inv_l = 1.f / l_i;
    float* outp = g_attn + ((size_t)(b * S_) + qt * 64 + r) * HID_ + h * HS_;
#pragma unroll
    for (int j4 = 0; j4 < 8; j4++) {
        float4 v;
        v.x = o[j4 * 4 + 0] * inv_l;
        v.y = o[j4 * 4 + 1] * inv_l;
        v.z = o[j4 * 4 + 2] * inv_l;
        v.w = o[j4 * 4 + 3] * inv_l;
        *(float4*)(outp + (q4 + 4 * j4) * 4) = v;
    }
}

// ---------------------------------------------------------------------------
extern "C" void kernel_launch(void* const* d_in, const int* in_sizes, int n_in,
                              void* d_out, int out_size)
{
    const float* x      = (const float*)d_in[0];
    // d_in[1] position_ids (= arange, applied analytically)
    // d_in[2] attention_mask (= causal, applied analytically)
    const float* Wqkv   = (const float*)d_in[3];
    const float* bqkv   = (const float*)d_in[4];
    const float* Wdense = (const float*)d_in[5];
    const float* bdense = (const float*)d_in[6];
    float* out = (float*)d_out;

    float* qkv;  cudaGetSymbolAddress((void**)&qkv, g_qkv);
    float* attn; cudaGetSymbolAddress((void**)&attn, g_attn);

    // 1) QKV GEMM: [4096,2048] @ [2048,6144] + bias
    {
        dim3 grid(QKV3 / 128, (B_ * S_) / 128);
        sgemm_bias<<<grid, 256>>>(x, Wqkv, bqkv, qkv, B_ * S_, QKV3, HID_);
    }

    // 2) RoPE in place
    {
        int n = B_ * S_ * NH_ * 16;
        rope_kernel<<<n / 256, 256>>>();
    }

    // 3) Flash attention
    {
        cudaFuncSetAttribute(attn_kernel, cudaFuncAttributeMaxDynamicSharedMemorySize, ATTN_SMEM);
        dim3 grid(S_ / 64, NH_, B_);
        attn_kernel<<<grid, 256, ATTN_SMEM>>>();
    }

    // 4) Dense GEMM: [4096,2048] @ [2048,2048] + bias -> d_out
    {
        dim3 grid(HID_ / 128, (B_ * S_) / 128);
        sgemm_bias<<<grid, 256>>>(attn, Wdense, bdense, out, B_ * S_, HID_, HID_);
    }
}

// round 3
// speedup vs baseline: 1.6180x; 1.6180x over previous
#include <cuda_runtime.h>
#include <math.h>

#define B_    2
#define S_    2048
#define HID_  2048
#define NH_   16
#define HS_   128
#define QKV3  6144   // 3*HID
#define HEAD3 384    // 3*HS

// Scratch (device globals — no allocation allowed)
__device__ float g_qkv[(size_t)B_ * S_ * QKV3];   // ~100 MB
__device__ float g_attn[(size_t)B_ * S_ * HID_];  // ~33 MB

// ---------------------------------------------------------------------------
// tf32 helpers
// ---------------------------------------------------------------------------
__device__ __forceinline__ unsigned f2tf(float x) {
    unsigned r;
    asm("cvt.rna.tf32.f32 %0, %1;" : "=r"(r) : "f"(x));
    return r;
}

__device__ __forceinline__ void mma_tf32(float* c, const unsigned* a, const unsigned* b) {
    asm volatile(
        "mma.sync.aligned.m16n8k8.row.col.f32.tf32.tf32.f32 "
        "{%0,%1,%2,%3}, {%4,%5,%6,%7}, {%8,%9}, {%0,%1,%2,%3};"
        : "+f"(c[0]), "+f"(c[1]), "+f"(c[2]), "+f"(c[3])
        : "r"(a[0]), "r"(a[1]), "r"(a[2]), "r"(a[3]), "r"(b[0]), "r"(b[1]));
}

// ---------------------------------------------------------------------------
// GEMM (tf32 tensor cores): C[M,N] = A[M,K] @ W[K,N] + bias[N], row-major.
// Block 256 thr (8 warps), tile 128x128x16. Warp tile 32x64 = 2 m16 x 8 n8.
// Smem row stride 136 (== 8 mod 32) -> conflict-free scalar fragment loads.
// ---------------------------------------------------------------------------
#define GSTRIDE 136

__global__ __launch_bounds__(256)
void gemm_tf32(const float* __restrict__ A, const float* __restrict__ W,
               const float* __restrict__ bias, float* __restrict__ C,
               int M, int N, int K)
{
    __shared__ unsigned As[16][GSTRIDE];
    __shared__ unsigned Bs[16][GSTRIDE];

    const int tid  = threadIdx.x;
    const int wid  = tid >> 5;
    const int lane = tid & 31;
    const int g    = lane >> 2;      // 0..7
    const int kq   = lane & 3;       // 0..3

    const int bm = blockIdx.y * 128;
    const int bn = blockIdx.x * 128;

    const int m_off = (wid >> 1) * 32;   // 0,32,64,96
    const int n_off = (wid & 1) * 64;    // 0,64

    // A loader: thread covers row = tid&127, cols half*8 .. +7
    const int row_a = tid & 127;
    const int col_a = (tid >> 7) * 8;
    const float* Aptr = A + (size_t)(bm + row_a) * K + col_a;

    // B loader: thread covers row = tid>>4, cols (tid&15)*8 .. +7
    const int row_b = tid >> 4;
    const int col_b = (tid & 15) * 8;
    const float* Wptr = W + (size_t)row_b * N + bn + col_b;

    float acc[2][8][4];
#pragma unroll
    for (int t = 0; t < 2; t++)
#pragma unroll
        for (int j = 0; j < 8; j++)
#pragma unroll
            for (int e = 0; e < 4; e++) acc[t][j][e] = 0.f;

    // prefetch tile 0
    float4 a0v = *(const float4*)(Aptr);
    float4 a1v = *(const float4*)(Aptr + 4);
    float4 b0v = *(const float4*)(Wptr);
    float4 b1v = *(const float4*)(Wptr + 4);

    for (int k0 = 0; k0 < K; k0 += 16) {
        // stage current tile into smem (convert to tf32)
        As[col_a + 0][row_a] = f2tf(a0v.x);
        As[col_a + 1][row_a] = f2tf(a0v.y);
        As[col_a + 2][row_a] = f2tf(a0v.z);
        As[col_a + 3][row_a] = f2tf(a0v.w);
        As[col_a + 4][row_a] = f2tf(a1v.x);
        As[col_a + 5][row_a] = f2tf(a1v.y);
        As[col_a + 6][row_a] = f2tf(a1v.z);
        As[col_a + 7][row_a] = f2tf(a1v.w);
        {
            uint4 u0 = { f2tf(b0v.x), f2tf(b0v.y), f2tf(b0v.z), f2tf(b0v.w) };
            uint4 u1 = { f2tf(b1v.x), f2tf(b1v.y), f2tf(b1v.z), f2tf(b1v.w) };
            *(uint4*)&Bs[row_b][col_b]     = u0;
            *(uint4*)&Bs[row_b][col_b + 4] = u1;
        }
        __syncthreads();

        // prefetch next tile (overlaps with mma below)
        if (k0 + 16 < K) {
            a0v = *(const float4*)(Aptr + k0 + 16);
            a1v = *(const float4*)(Aptr + k0 + 20);
            b0v = *(const float4*)(Wptr + (size_t)(k0 + 16) * N);
            b1v = *(const float4*)(Wptr + (size_t)(k0 + 16) * N + 4);
        }

#pragma unroll
        for (int kk = 0; kk < 2; kk++) {
            const int kb = kk * 8 + kq;
            unsigned af[2][4];
#pragma unroll
            for (int t = 0; t < 2; t++) {
                int m = m_off + t * 16 + g;
                af[t][0] = As[kb][m];
                af[t][1] = As[kb][m + 8];
                af[t][2] = As[kb + 4][m];
                af[t][3] = As[kb + 4][m + 8];
            }
            unsigned bf[8][2];
#pragma unroll
            for (int j = 0; j < 8; j++) {
                int n = n_off + j * 8 + g;
                bf[j][0] = Bs[kb][n];
                bf[j][1] = Bs[kb + 4][n];
            }
#pragma unroll
            for (int t = 0; t < 2; t++)
#pragma unroll
                for (int j = 0; j < 8; j++)
                    mma_tf32(acc[t][j], af[t], bf[j]);
        }
        __syncthreads();
    }

    // epilogue: c0,c1 at (row, 2*kq+{0,1}); c2,c3 at (row+8, same cols)
#pragma unroll
    for (int t = 0; t < 2; t++) {
        int row = bm + m_off + t * 16 + g;
#pragma unroll
        for (int j = 0; j < 8; j++) {
            int col = bn + n_off + j * 8 + 2 * kq;
            float2 bb = *(const float2*)(bias + col);
            float2 v0 = { acc[t][j][0] + bb.x, acc[t][j][1] + bb.y };
            float2 v1 = { acc[t][j][2] + bb.x, acc[t][j][3] + bb.y };
            *(float2*)(C + (size_t)row * N + col)       = v0;
            *(float2*)(C + (size_t)(row + 8) * N + col) = v1;
        }
    }
}

// ---------------------------------------------------------------------------
// RoPE in place on q and k (first ROT=32 dims, half=16), positions = s.
// ---------------------------------------------------------------------------
__global__ void rope_kernel()
{
    int idx = blockIdx.x * blockDim.x + threadIdx.x;
    int d = idx & 15;
    int h = (idx >> 4) & (NH_ - 1);
    int s = (idx >> 8) & (S_ - 1);
    int b = idx >> 19;
    if (b >= B_) return;

    float inv = powf(10000.f, -((float)(2 * d) / 32.f));
    float ang = (float)s * inv;
    float c = cosf(ang);
    float sn = sinf(ang);

    float* base = g_qkv + ((size_t)(b * S_ + s)) * QKV3 + h * HEAD3;
    float x1 = base[d], x2 = base[d + 16];
    base[d]      = x1 * c - x2 * sn;
    base[d + 16] = x2 * c + x1 * sn;
    x1 = base[HS_ + d]; x2 = base[HS_ + d + 16];
    base[HS_ + d]      = x1 * c - x2 * sn;
    base[HS_ + d + 16] = x2 * c + x1 * sn;
}

// ---------------------------------------------------------------------------
// Flash attention (fp32, causal). Q-tile 128 rows, KV-tile 64, 256 threads.
// Thread t: base row r=t>>2 (owns rows r and r+64), quad lane q4=t&3.
//   S-cols: c = i*4+q4 (i<16);  O float4-chunks: d4 = q4+4*j4 (j4<8)
// ---------------------------------------------------------------------------
#define RS 132   // row stride (floats) for Q/K/V tiles
#define PS 65    // row stride for P tile
#define ATTN_SMEM ((128 * RS + 2 * 64 * RS + 128 * PS) * 4)

__global__ __launch_bounds__(256)
void attn_kernel()
{
    extern __shared__ float sm[];
    float* Qs = sm;                     // 128*RS
    float* Ks = Qs + 128 * RS;          // 64*RS
    float* Vs = Ks + 64 * RS;           // 64*RS
    float* Ps = Vs + 64 * RS;           // 128*PS

    const int b = blockIdx.z, h = blockIdx.y, qt = blockIdx.x;
    const int tid = threadIdx.x;
    const int r = tid >> 2;
    const int q4 = tid & 3;
    const float scale = 0.08838834764831845f;  // 1/sqrt(128)

    const size_t qkvbase = (size_t)b * S_ * QKV3 + (size_t)h * HEAD3;

    // load Q tile (128 rows x 128)
    for (int e = tid; e < 128 * 32; e += 256) {
        int row = e >> 5, c4 = e & 31;
        *(float4*)&Qs[row * RS + c4 * 4] =
            *(const float4*)(g_qkv + qkvbase + (size_t)(qt * 128 + row) * QKV3 + c4 * 4);
    }

    float o[2][32];
#pragma unroll
    for (int rr = 0; rr < 2; rr++)
#pragma unroll
        for (int i = 0; i < 32; i++) o[rr][i] = 0.f;
    float m_i[2] = { -1e30f, -1e30f };
    float l_i[2] = { 0.f, 0.f };

    const int rg0 = qt * 128 + r;
    const int rg1 = rg0 + 64;
    const int ntiles = 2 * qt + 2;

    for (int kt = 0; kt < ntiles; kt++) {
        __syncthreads();
        for (int e = tid; e < 64 * 32; e += 256) {
            int row = e >> 5, c4 = e & 31;
            const float* gp = g_qkv + qkvbase + (size_t)(kt * 64 + row) * QKV3 + c4 * 4;
            *(float4*)&Ks[row * RS + c4 * 4] = *(const float4*)(gp + HS_);
            *(float4*)&Vs[row * RS + c4 * 4] = *(const float4*)(gp + 2 * HS_);
        }
        __syncthreads();

        // S = Q K^T (two row-sets x 16 cols per thread)
        float sacc[2][16];
#pragma unroll
        for (int rr = 0; rr < 2; rr++)
#pragma unroll
            for (int i = 0; i < 16; i++) sacc[rr][i] = 0.f;

#pragma unroll 4
        for (int d4 = 0; d4 < 32; d4++) {
            float4 q0 = *(float4*)&Qs[r * RS + d4 * 4];
            float4 q1 = *(float4*)&Qs[(r + 64) * RS + d4 * 4];
#pragma unroll
            for (int i = 0; i < 16; i++) {
                float4 kv = *(float4*)&Ks[(i * 4 + q4) * RS + d4 * 4];
                sacc[0][i] += q0.x * kv.x + q0.y * kv.y + q0.z * kv.z + q0.w * kv.w;
                sacc[1][i] += q1.x * kv.x + q1.y * kv.y + q1.z * kv.z + q1.w * kv.w;
            }
        }

        // scale + causal mask, online softmax per row-set
#pragma unroll
        for (int rr = 0; rr < 2; rr++) {
            int rg = rr ? rg1 : rg0;
#pragma unroll
            for (int i = 0; i < 16; i++) {
                int cg = kt * 64 + i * 4 + q4;
                sacc[rr][i] = (cg <= rg) ? sacc[rr][i] * scale : -1e30f;
            }
            float tmax = sacc[rr][0];
#pragma unroll
            for (int i = 1; i < 16; i++) tmax = fmaxf(tmax, sacc[rr][i]);
            tmax = fmaxf(tmax, __shfl_xor_sync(0xffffffffu, tmax, 1));
            tmax = fmaxf(tmax, __shfl_xor_sync(0xffffffffu, tmax, 2));
            float m_new = fmaxf(m_i[rr], tmax);
            float alpha = expf(m_i[rr] - m_new);

            float psum = 0.f;
#pragma unroll
            for (int i = 0; i < 16; i++) {
                float p = expf(sacc[rr][i] - m_new);
                sacc[rr][i] = p;
                psum += p;
            }
            psum += __shfl_xor_sync(0xffffffffu, psum, 1);
            psum += __shfl_xor_sync(0xffffffffu, psum, 2);

            l_i[rr] = l_i[rr] * alpha + psum;
            m_i[rr] = m_new;
#pragma unroll
            for (int j = 0; j < 32; j++) o[rr][j] *= alpha;

#pragma unroll
            for (int i = 0; i < 16; i++)
                Ps[(r + rr * 64) * PS + i * 4 + q4] = sacc[rr][i];
        }
        __syncwarp();   // P exchange is intra-quad (same warp)

        // O += P @ V
        for (int c = 0; c < 64; c++) {
            float pr0 = Ps[r * PS + c];
            float pr1 = Ps[(r + 64) * PS + c];
#pragma unroll
            for (int j4 = 0; j4 < 8; j4++) {
                float4 vv = *(float4*)&Vs[c * RS + (q4 + 4 * j4) * 4];
                o[0][j4 * 4 + 0] += pr0 * vv.x;
                o[0][j4 * 4 + 1] += pr0 * vv.y;
                o[0][j4 * 4 + 2] += pr0 * vv.z;
                o[0][j4 * 4 + 3] += pr0 * vv.w;
                o[1][j4 * 4 + 0] += pr1 * vv.x;
                o[1][j4 * 4 + 1] += pr1 * vv.y;
                o[1][j4 * 4 + 2] += pr1 * vv.z;
                o[1][j4 * 4 + 3] += pr1 * vv.w;
            }
        }
    }

    // epilogue: normalize, write to g_attn [B,S,HID]
#pragma unroll
    for (int rr = 0; rr < 2; rr++) {
        float inv_l = 1.f / l_i[rr];
        float* outp = g_attn + ((size_t)(b * S_) + qt * 128 + rr * 64 + r) * HID_ + h * HS_;
#pragma unroll
        for (int j4 = 0; j4 < 8; j4++) {
            float4 v;
            v.x = o[rr][j4 * 4 + 0] * inv_l;
            v.y = o[rr][j4 * 4 + 1] * inv_l;
            v.z = o[rr][j4 * 4 + 2] * inv_l;
            v.w = o[rr][j4 * 4 + 3] * inv_l;
            *(float4*)(outp + (q4 + 4 * j4) * 4) = v;
        }
    }
}

// ---------------------------------------------------------------------------
extern "C" void kernel_launch(void* const* d_in, const int* in_sizes, int n_in,
                              void* d_out, int out_size)
{
    const float* x      = (const float*)d_in[0];
    // d_in[1] position_ids (= arange, applied analytically)
    // d_in[2] attention_mask (= causal, applied analytically)
    const float* Wqkv   = (const float*)d_in[3];
    const float* bqkv   = (const float*)d_in[4];
    const float* Wdense = (const float*)d_in[5];
    const float* bdense = (const float*)d_in[6];
    float* out = (float*)d_out;

    float* qkv;  cudaGetSymbolAddress((void**)&qkv, g_qkv);
    float* attn; cudaGetSymbolAddress((void**)&attn, g_attn);

    // 1) QKV GEMM: [4096,2048] @ [2048,6144] + bias  (tf32 tensor cores)
    {
        dim3 grid(QKV3 / 128, (B_ * S_) / 128);
        gemm_tf32<<<grid, 256>>>(x, Wqkv, bqkv, qkv, B_ * S_, QKV3, HID_);
    }

    // 2) RoPE in place
    {
        int n = B_ * S_ * NH_ * 16;
        rope_kernel<<<n / 256, 256>>>();
    }

    // 3) Flash attention
    {
        cudaFuncSetAttribute(attn_kernel, cudaFuncAttributeMaxDynamicSharedMemorySize, ATTN_SMEM);
        dim3 grid(S_ / 128, NH_, B_);
        attn_kernel<<<grid, 256, ATTN_SMEM>>>();
    }

    // 4) Dense GEMM: [4096,2048] @ [2048,2048] + bias -> d_out
    {
        dim3 grid(HID_ / 128, (B_ * S_) / 128);
        gemm_tf32<<<grid, 256>>>(attn, Wdense, bdense, out, B_ * S_, HID_, HID_);
    }
}

// round 4
// speedup vs baseline: 2.5110x; 1.5519x over previous
#include <cuda_runtime.h>
#include <math.h>

#define B_    2
#define S_    2048
#define HID_  2048
#define NH_   16
#define HS_   128
#define QKV3  6144   // 3*HID
#define HEAD3 384    // 3*HS

// Scratch (device globals — no allocation allowed)
__device__ float g_qkv[(size_t)B_ * S_ * QKV3];   // ~100 MB
__device__ float g_attn[(size_t)B_ * S_ * HID_];  // ~33 MB

// ---------------------------------------------------------------------------
// tf32 helpers
// ---------------------------------------------------------------------------
__device__ __forceinline__ unsigned f2tf(float x) {
    unsigned r;
    asm("cvt.rna.tf32.f32 %0, %1;" : "=r"(r) : "f"(x));
    return r;
}

__device__ __forceinline__ void mma_tf32(float* c, const unsigned* a, const unsigned* b) {
    asm volatile(
        "mma.sync.aligned.m16n8k8.row.col.f32.tf32.tf32.f32 "
        "{%0,%1,%2,%3}, {%4,%5,%6,%7}, {%8,%9}, {%0,%1,%2,%3};"
        : "+f"(c[0]), "+f"(c[1]), "+f"(c[2]), "+f"(c[3])
        : "r"(a[0]), "r"(a[1]), "r"(a[2]), "r"(a[3]), "r"(b[0]), "r"(b[1]));
}

// ---------------------------------------------------------------------------
// GEMM (tf32 tensor cores, 2-stage double buffer):
// C[M,N] = A[M,K] @ W[K,N] + bias[N], row-major.
// Block 256 thr (8 warps), tile 128x128x16. Warp tile 32x64 = 2 m16 x 8 n8.
// Smem row stride 136 (== 8 mod 32) -> conflict-free scalar fragment loads.
// ---------------------------------------------------------------------------
#define GSTRIDE 136

__global__ __launch_bounds__(256)
void gemm_tf32(const float* __restrict__ A, const float* __restrict__ W,
               const float* __restrict__ bias, float* __restrict__ C,
               int M, int N, int K)
{
    __shared__ unsigned As[2][16][GSTRIDE];
    __shared__ unsigned Bs[2][16][GSTRIDE];

    const int tid  = threadIdx.x;
    const int wid  = tid >> 5;
    const int lane = tid & 31;
    const int g    = lane >> 2;      // 0..7
    const int kq   = lane & 3;       // 0..3

    const int bm = blockIdx.y * 128;
    const int bn = blockIdx.x * 128;

    const int m_off = (wid >> 1) * 32;   // 0,32,64,96
    const int n_off = (wid & 1) * 64;    // 0,64

    const int row_a = tid & 127;
    const int col_a = (tid >> 7) * 8;
    const float* Aptr = A + (size_t)(bm + row_a) * K + col_a;

    const int row_b = tid >> 4;
    const int col_b = (tid & 15) * 8;
    const float* Wptr = W + (size_t)row_b * N + bn + col_b;

    float acc[2][8][4];
#pragma unroll
    for (int t = 0; t < 2; t++)
#pragma unroll
        for (int j = 0; j < 8; j++)
#pragma unroll
            for (int e = 0; e < 4; e++) acc[t][j][e] = 0.f;

    float4 a0v, a1v, b0v, b1v;

    // prologue: load + stage tile 0
    a0v = *(const float4*)(Aptr);
    a1v = *(const float4*)(Aptr + 4);
    b0v = *(const float4*)(Wptr);
    b1v = *(const float4*)(Wptr + 4);
    {
        As[0][col_a + 0][row_a] = f2tf(a0v.x);
        As[0][col_a + 1][row_a] = f2tf(a0v.y);
        As[0][col_a + 2][row_a] = f2tf(a0v.z);
        As[0][col_a + 3][row_a] = f2tf(a0v.w);
        As[0][col_a + 4][row_a] = f2tf(a1v.x);
        As[0][col_a + 5][row_a] = f2tf(a1v.y);
        As[0][col_a + 6][row_a] = f2tf(a1v.z);
        As[0][col_a + 7][row_a] = f2tf(a1v.w);
        uint4 u0 = { f2tf(b0v.x), f2tf(b0v.y), f2tf(b0v.z), f2tf(b0v.w) };
        uint4 u1 = { f2tf(b1v.x), f2tf(b1v.y), f2tf(b1v.z), f2tf(b1v.w) };
        *(uint4*)&Bs[0][row_b][col_b]     = u0;
        *(uint4*)&Bs[0][row_b][col_b + 4] = u1;
    }
    __syncthreads();

    const int nk = K >> 4;
    for (int t = 0; t < nk; t++) {
        const int p = t & 1;
        const int k0 = (t + 1) << 4;

        // prefetch next tile (LDG issues before MMAs)
        if (t + 1 < nk) {
            a0v = *(const float4*)(Aptr + k0);
            a1v = *(const float4*)(Aptr + k0 + 4);
            b0v = *(const float4*)(Wptr + (size_t)k0 * N);
            b1v = *(const float4*)(Wptr + (size_t)k0 * N + 4);
        }

#pragma unroll
        for (int kk = 0; kk < 2; kk++) {
            const int kb = kk * 8 + kq;
            unsigned af[2][4];
#pragma unroll
            for (int tt = 0; tt < 2; tt++) {
                int m = m_off + tt * 16 + g;
                af[tt][0] = As[p][kb][m];
                af[tt][1] = As[p][kb][m + 8];
                af[tt][2] = As[p][kb + 4][m];
                af[tt][3] = As[p][kb + 4][m + 8];
            }
            unsigned bf[8][2];
#pragma unroll
            for (int j = 0; j < 8; j++) {
                int n = n_off + j * 8 + g;
                bf[j][0] = Bs[p][kb][n];
                bf[j][1] = Bs[p][kb + 4][n];
            }
#pragma unroll
            for (int tt = 0; tt < 2; tt++)
#pragma unroll
                for (int j = 0; j < 8; j++)
                    mma_tf32(acc[tt][j], af[tt], bf[j]);
        }

        // stage next tile into the other buffer
        if (t + 1 < nk) {
            const int q = p ^ 1;
            As[q][col_a + 0][row_a] = f2tf(a0v.x);
            As[q][col_a + 1][row_a] = f2tf(a0v.y);
            As[q][col_a + 2][row_a] = f2tf(a0v.z);
            As[q][col_a + 3][row_a] = f2tf(a0v.w);
            As[q][col_a + 4][row_a] = f2tf(a1v.x);
            As[q][col_a + 5][row_a] = f2tf(a1v.y);
            As[q][col_a + 6][row_a] = f2tf(a1v.z);
            As[q][col_a + 7][row_a] = f2tf(a1v.w);
            uint4 u0 = { f2tf(b0v.x), f2tf(b0v.y), f2tf(b0v.z), f2tf(b0v.w) };
            uint4 u1 = { f2tf(b1v.x), f2tf(b1v.y), f2tf(b1v.z), f2tf(b1v.w) };
            *(uint4*)&Bs[q][row_b][col_b]     = u0;
            *(uint4*)&Bs[q][row_b][col_b + 4] = u1;
        }
        __syncthreads();
    }

    // epilogue: c0,c1 at (row, 2*kq+{0,1}); c2,c3 at (row+8, same cols)
#pragma unroll
    for (int t = 0; t < 2; t++) {
        int row = bm + m_off + t * 16 + g;
#pragma unroll
        for (int j = 0; j < 8; j++) {
            int col = bn + n_off + j * 8 + 2 * kq;
            float2 bb = *(const float2*)(bias + col);
            float2 v0 = { acc[t][j][0] + bb.x, acc[t][j][1] + bb.y };
            float2 v1 = { acc[t][j][2] + bb.x, acc[t][j][3] + bb.y };
            *(float2*)(C + (size_t)row * N + col)       = v0;
            *(float2*)(C + (size_t)(row + 8) * N + col) = v1;
        }
    }
}

// ---------------------------------------------------------------------------
// RoPE in place on q and k (first ROT=32 dims, half=16), positions = s.
// ---------------------------------------------------------------------------
__global__ void rope_kernel()
{
    int idx = blockIdx.x * blockDim.x + threadIdx.x;
    int d = idx & 15;
    int h = (idx >> 4) & (NH_ - 1);
    int s = (idx >> 8) & (S_ - 1);
    int b = idx >> 19;
    if (b >= B_) return;

    float inv = powf(10000.f, -((float)(2 * d) / 32.f));
    float ang = (float)s * inv;
    float c = cosf(ang);
    float sn = sinf(ang);

    float* base = g_qkv + ((size_t)(b * S_ + s)) * QKV3 + h * HEAD3;
    float x1 = base[d], x2 = base[d + 16];
    base[d]      = x1 * c - x2 * sn;
    base[d + 16] = x2 * c + x1 * sn;
    x1 = base[HS_ + d]; x2 = base[HS_ + d + 16];
    base[HS_ + d]      = x1 * c - x2 * sn;
    base[HS_ + d + 16] = x2 * c + x1 * sn;
}

// ---------------------------------------------------------------------------
// Flash attention, tf32 tensor cores. Q-tile 128 (8 warps x 16 rows),
// KV-tile 64, HS=128. All tiles stored in smem as tf32 (unsigned).
// Strides chosen for conflict-free scalar fragment LDS:
//   Q/K stride 132 (bank = 4g+kq), V stride 136 (bank = 8kq+g), P stride 68.
// ---------------------------------------------------------------------------
#define AQ_S 132
#define AV_S 136
#define AP_S 68
#define ATTN_SMEM ((128 * AQ_S + 64 * AQ_S + 64 * AV_S + 128 * AP_S) * 4)

__global__ __launch_bounds__(256)
void attn_kernel()
{
    extern __shared__ unsigned smu[];
    unsigned* Qs = smu;                  // 128 x AQ_S
    unsigned* Ks = Qs + 128 * AQ_S;      // 64 x AQ_S
    unsigned* Vs = Ks + 64 * AQ_S;       // 64 x AV_S  (row-major [c][d])
    unsigned* Ps = Vs + 64 * AV_S;       // 128 x AP_S

    const int b = blockIdx.z, h = blockIdx.y, qt = blockIdx.x;
    const int tid  = threadIdx.x;
    const int wid  = tid >> 5;
    const int lane = tid & 31;
    const int g    = lane >> 2;
    const int kq   = lane & 3;
    const int wb   = wid * 16;          // warp's Q-row base within tile
    const float scale = 0.08838834764831845f;  // 1/sqrt(128)

    const size_t qkvbase = (size_t)b * S_ * QKV3 + (size_t)h * HEAD3;

    // load Q tile (128 rows x 128), convert to tf32
    for (int e = tid; e < 128 * 32; e += 256) {
        int row = e >> 5, c4 = e & 31;
        float4 v = *(const float4*)(g_qkv + qkvbase + (size_t)(qt * 128 + row) * QKV3 + c4 * 4);
        uint4 u = { f2tf(v.x), f2tf(v.y), f2tf(v.z), f2tf(v.w) };
        *(uint4*)&Qs[row * AQ_S + c4 * 4] = u;
    }

    float o[16][4];
#pragma unroll
    for (int n = 0; n < 16; n++)
#pragma unroll
        for (int e = 0; e < 4; e++) o[n][e] = 0.f;
    float m_i[2] = { -1e30f, -1e30f };
    float l_i[2] = { 0.f, 0.f };

    const int r0 = qt * 128 + wb + g;    // global row of c0/c1
    const int r1 = r0 + 8;               // global row of c2/c3
    const int ntiles = 2 * qt + 2;

    for (int kt = 0; kt < ntiles; kt++) {
        __syncthreads();
        // load K,V tiles (64 x 128 each), convert to tf32
        for (int e = tid; e < 64 * 32; e += 256) {
            int row = e >> 5, c4 = e & 31;
            const float* gp = g_qkv + qkvbase + (size_t)(kt * 64 + row) * QKV3 + c4 * 4;
            float4 kv = *(const float4*)(gp + HS_);
            float4 vv = *(const float4*)(gp + 2 * HS_);
            uint4 ku = { f2tf(kv.x), f2tf(kv.y), f2tf(kv.z), f2tf(kv.w) };
            uint4 vu = { f2tf(vv.x), f2tf(vv.y), f2tf(vv.z), f2tf(vv.w) };
            *(uint4*)&Ks[row * AQ_S + c4 * 4] = ku;
            *(uint4*)&Vs[row * AV_S + c4 * 4] = vu;
        }
        __syncthreads();

        // ---- S = Q K^T : warp computes 16x64 via 8 n-tiles x 16 k-steps
        float sacc[8][4];
#pragma unroll
        for (int j = 0; j < 8; j++)
#pragma unroll
            for (int e = 0; e < 4; e++) sacc[j][e] = 0.f;

#pragma unroll
        for (int s = 0; s < 16; s++) {
            const int kb = s * 8 + kq;
            unsigned a[4];
            a[0] = Qs[(wb + g) * AQ_S + kb];
            a[1] = Qs[(wb + g + 8) * AQ_S + kb];
            a[2] = Qs[(wb + g) * AQ_S + kb + 4];
            a[3] = Qs[(wb + g + 8) * AQ_S + kb + 4];
#pragma unroll
            for (int j = 0; j < 8; j++) {
                unsigned bfr[2];
                bfr[0] = Ks[(j * 8 + g) * AQ_S + kb];
                bfr[1] = Ks[(j * 8 + g) * AQ_S + kb + 4];
                mma_tf32(sacc[j], a, bfr);
            }
        }

        // ---- scale + causal mask
        const bool needmask = (kt * 64 + 63) > (qt * 128 + wb);
        if (needmask) {
#pragma unroll
            for (int j = 0; j < 8; j++) {
                int col = kt * 64 + j * 8 + 2 * kq;
#pragma unroll
                for (int e = 0; e < 2; e++) {
                    sacc[j][e]     = (col + e <= r0) ? sacc[j][e] * scale     : -1e30f;
                    sacc[j][2 + e] = (col + e <= r1) ? sacc[j][2 + e] * scale : -1e30f;
                }
            }
        } else {
#pragma unroll
            for (int j = 0; j < 8; j++)
#pragma unroll
                for (int e = 0; e < 4; e++) sacc[j][e] *= scale;
        }

        // ---- online softmax per row-set (rr=0: rows g / elems 0,1; rr=1: rows g+8)
#pragma unroll
        for (int rr = 0; rr < 2; rr++) {
            float tmax = -1e30f;
#pragma unroll
            for (int j = 0; j < 8; j++)
                tmax = fmaxf(tmax, fmaxf(sacc[j][rr * 2], sacc[j][rr * 2 + 1]));
            tmax = fmaxf(tmax, __shfl_xor_sync(0xffffffffu, tmax, 1));
            tmax = fmaxf(tmax, __shfl_xor_sync(0xffffffffu, tmax, 2));
            float m_new = fmaxf(m_i[rr], tmax);
            float alpha = __expf(m_i[rr] - m_new);

            float psum = 0.f;
#pragma unroll
            for (int j = 0; j < 8; j++) {
                float p0 = __expf(sacc[j][rr * 2]     - m_new);
                float p1 = __expf(sacc[j][rr * 2 + 1] - m_new);
                sacc[j][rr * 2]     = p0;
                sacc[j][rr * 2 + 1] = p1;
                psum += p0 + p1;
            }
            psum += __shfl_xor_sync(0xffffffffu, psum, 1);
            psum += __shfl_xor_sync(0xffffffffu, psum, 2);

            l_i[rr] = l_i[rr] * alpha + psum;
            m_i[rr] = m_new;
#pragma unroll
            for (int n = 0; n < 16; n++) {
                o[n][rr * 2]     *= alpha;
                o[n][rr * 2 + 1] *= alpha;
            }
        }

        // ---- write P (tf32) to this warp's smem region
#pragma unroll
        for (int j = 0; j < 8; j++) {
            int cbase = j * 8 + 2 * kq;
            Ps[(wb + g) * AP_S + cbase]         = f2tf(sacc[j][0]);
            Ps[(wb + g) * AP_S + cbase + 1]     = f2tf(sacc[j][1]);
            Ps[(wb + g + 8) * AP_S + cbase]     = f2tf(sacc[j][2]);
            Ps[(wb + g + 8) * AP_S + cbase + 1] = f2tf(sacc[j][3]);
        }
        __syncwarp();

        // ---- O += P V : 16 n-tiles (d=128) x 8 k-steps (c=64)
#pragma unroll
        for (int s = 0; s < 8; s++) {
            const int kb = s * 8 + kq;
            unsigned a[4];
            a[0] = Ps[(wb + g) * AP_S + kb];
            a[1] = Ps[(wb + g + 8) * AP_S + kb];
            a[2] = Ps[(wb + g) * AP_S + kb + 4];
            a[3] = Ps[(wb + g + 8) * AP_S + kb + 4];
#pragma unroll
            for (int n = 0; n < 16; n++) {
                unsigned bfr[2];
                bfr[0] = Vs[kb * AV_S + n * 8 + g];
                bfr[1] = Vs[(kb + 4) * AV_S + n * 8 + g];
                mma_tf32(o[n], a, bfr);
            }
        }
    }

    // ---- epilogue: normalize, write to g_attn [B,S,HID]
    const float invl0 = 1.f / l_i[0];
    const float invl1 = 1.f / l_i[1];
    float* out0 = g_attn + ((size_t)(b * S_) + r0) * HID_ + h * HS_;
    float* out1 = g_attn + ((size_t)(b * S_) + r1) * HID_ + h * HS_;
#pragma unroll
    for (int n = 0; n < 16; n++) {
        int col = n * 8 + 2 * kq;
        float2 v0 = { o[n][0] * invl0, o[n][1] * invl0 };
        float2 v1 = { o[n][2] * invl1, o[n][3] * invl1 };
        *(float2*)(out0 + col) = v0;
        *(float2*)(out1 + col) = v1;
    }
}

// ---------------------------------------------------------------------------
extern "C" void kernel_launch(void* const* d_in, const int* in_sizes, int n_in,
                              void* d_out, int out_size)
{
    const float* x      = (const float*)d_in[0];
    // d_in[1] position_ids (= arange, applied analytically)
    // d_in[2] attention_mask (= causal, applied analytically)
    const float* Wqkv   = (const float*)d_in[3];
    const float* bqkv   = (const float*)d_in[4];
    const float* Wdense = (const float*)d_in[5];
    const float* bdense = (const float*)d_in[6];
    float* out = (float*)d_out;

    float* qkv;  cudaGetSymbolAddress((void**)&qkv, g_qkv);
    float* attn; cudaGetSymbolAddress((void**)&attn, g_attn);

    // 1) QKV GEMM: [4096,2048] @ [2048,6144] + bias  (tf32 tensor cores)
    {
        dim3 grid(QKV3 / 128, (B_ * S_) / 128);
        gemm_tf32<<<grid, 256>>>(x, Wqkv, bqkv, qkv, B_ * S_, QKV3, HID_);
    }

    // 2) RoPE in place
    {
        int n = B_ * S_ * NH_ * 16;
        rope_kernel<<<n / 256, 256>>>();
    }

    // 3) Flash attention (tf32 tensor cores)
    {
        cudaFuncSetAttribute(attn_kernel, cudaFuncAttributeMaxDynamicSharedMemorySize, ATTN_SMEM);
        dim3 grid(S_ / 128, NH_, B_);
        attn_kernel<<<grid, 256, ATTN_SMEM>>>();
    }

    // 4) Dense GEMM: [4096,2048] @ [2048,2048] + bias -> d_out
    {
        dim3 grid(HID_ / 128, (B_ * S_) / 128);
        gemm_tf32<<<grid, 256>>>(attn, Wdense, bdense, out, B_ * S_, HID_, HID_);
    }
}

// round 7
// speedup vs baseline: 3.7088x; 1.4770x over previous
#include <cuda_runtime.h>
#include <math.h>
#include <stdint.h>

#define B_    2
#define S_    2048
#define HID_  2048
#define NH_   16
#define HS_   128
#define QKV3  6144   // 3*HID
#define HEAD3 384    // 3*HS
#define K_    2048   // GEMM reduction dim (both GEMMs)

// Scratch (device globals — no allocation allowed)
__device__ float g_qkv[(size_t)B_ * S_ * QKV3];    // ~100 MB
__device__ float g_attn[(size_t)B_ * S_ * HID_];   // ~33 MB
__device__ float g_xr[(size_t)B_ * S_ * HID_];     // x, tf32-rounded
__device__ float g_wqkvT[(size_t)QKV3 * HID_];     // Wqkv^T, tf32-rounded
__device__ float g_wdT[(size_t)HID_ * HID_];       // Wdense^T, tf32-rounded

// ---------------------------------------------------------------------------
// helpers
// ---------------------------------------------------------------------------
__device__ __forceinline__ unsigned f2tf(float x) {
    unsigned r;
    asm("cvt.rna.tf32.f32 %0, %1;" : "=r"(r) : "f"(x));
    return r;
}
__device__ __forceinline__ float f2tf_f(float x) { return __uint_as_float(f2tf(x)); }

__device__ __forceinline__ void mma_tf32(float* c, const unsigned* a, const unsigned* b) {
    asm volatile(
        "mma.sync.aligned.m16n8k8.row.col.f32.tf32.tf32.f32 "
        "{%0,%1,%2,%3}, {%4,%5,%6,%7}, {%8,%9}, {%0,%1,%2,%3};"
        : "+f"(c[0]), "+f"(c[1]), "+f"(c[2]), "+f"(c[3])
        : "r"(a[0]), "r"(a[1]), "r"(a[2]), "r"(a[3]), "r"(b[0]), "r"(b[1]));
}

__device__ __forceinline__ uint32_t smem_u32(const void* p) {
    uint32_t a;
    asm("{ .reg .u64 t; cvta.to.shared.u64 t, %1; cvt.u32.u64 %0, t; }" : "=r"(a) : "l"(p));
    return a;
}

__device__ __forceinline__ void cp16(uint32_t dst, const void* src) {
    asm volatile("cp.async.ca.shared.global [%0], [%1], 16;" :: "r"(dst), "l"(src) : "memory");
}
#define CP_COMMIT() asm volatile("cp.async.commit_group;" ::: "memory")
#define CP_WAIT1()  asm volatile("cp.async.wait_group 1;" ::: "memory")

// ---------------------------------------------------------------------------
// Pre-pass kernels: tf32-rna rounding (and transpose for weights)
// ---------------------------------------------------------------------------
__global__ void round_copy(const float* __restrict__ src, float* __restrict__ dst, int n4)
{
    int i = blockIdx.x * blockDim.x + threadIdx.x;
    if (i >= n4) return;
    float4 v = ((const float4*)src)[i];
    float4 o = { f2tf_f(v.x), f2tf_f(v.y), f2tf_f(v.z), f2tf_f(v.w) };
    ((float4*)dst)[i] = o;
}

// src [rows][cols] -> dst [cols][rows], tf32-rna rounded
__global__ void transpose_round(const float* __restrict__ src, float* __restrict__ dst,
                                int rows, int cols)
{
    __shared__ float tile[32][33];
    int bx = blockIdx.x * 32;   // col base
    int by = blockIdx.y * 32;   // row base
    int tx = threadIdx.x, ty = threadIdx.y;
#pragma unroll
    for (int j = 0; j < 4; j++)
        tile[ty + j * 8][tx] = src[(size_t)(by + ty + j * 8) * cols + bx + tx];
    __syncthreads();
#pragma unroll
    for (int j = 0; j < 4; j++)
        dst[(size_t)(bx + ty + j * 8) * rows + by + tx] = f2tf_f(tile[tx][ty + j * 8]);
}

// ---------------------------------------------------------------------------
// tf32 mma.sync GEMM with cp.async 3-stage pipeline.
// C[M,N] = A[M,K] @ Bt[N,K]^T + bias[N].  A, Bt pre-rounded to tf32-rna.
// Block 256 thr (8 warps), tile 128x128x32. Warp tile 32x64 = 2 m16 x 8 n8.
// Smem: XOR-swizzled rows (32 floats = 128B), chunk c of row r at
//   r*128 + ((c ^ (r&7))<<4) bytes. Stage = A(16KB)+B(16KB) = 32KB, x3 = 96KB.
// Fragment banks: 4*((2kk+h)^g)+kq -> permutation over 32 lanes, conflict-free.
// ---------------------------------------------------------------------------
#define STG_FLOATS 8192            // floats per stage (A 4096 + B 4096)
#define SM_GEMM_TOTAL (3 * STG_FLOATS * 4)   // 98304

__global__ __launch_bounds__(256)
void gemm_mma(const float* __restrict__ A, const float* __restrict__ Bt,
              const float* __restrict__ bias, float* __restrict__ C, int N)
{
    extern __shared__ float smf[];
    const uint32_t sb = smem_u32(smf);

    const int tid  = threadIdx.x;
    const int wid  = tid >> 5;
    const int lane = tid & 31;
    const int g    = lane >> 2;      // 0..7
    const int kq   = lane & 3;       // 0..3

    const int bm = blockIdx.y * 128;
    const int bn = blockIdx.x * 128;
    const int m_off = (wid >> 1) * 32;   // 0,32,64,96
    const int n_off = (wid & 1) * 64;    // 0,64

    // loader: thread covers (row = idx>>3, chunk c = idx&7), idx = tid + i*256
    const int l_row = tid >> 3;          // 0..31 (+32*i)
    const int l_c   = tid & 7;

    float acc[2][8][4];
#pragma unroll
    for (int t = 0; t < 2; t++)
#pragma unroll
        for (int j = 0; j < 8; j++)
#pragma unroll
            for (int e = 0; e < 4; e++) acc[t][j][e] = 0.f;

    const int NKT = K_ / 32;   // 64

    auto issue = [&](int kt) {
        const uint32_t stg = sb + (uint32_t)(kt % 3) * (STG_FLOATS * 4);
#pragma unroll
        for (int i = 0; i < 4; i++) {
            int row = l_row + i * 32;
            uint32_t soff = (uint32_t)(row * 128 + ((l_c ^ (row & 7)) << 4));
            cp16(stg + soff,
                 A + (size_t)(bm + row) * K_ + kt * 32 + l_c * 4);
            cp16(stg + 16384u + soff,
                 Bt + (size_t)(bn + row) * K_ + kt * 32 + l_c * 4);
        }
    };

    issue(0); CP_COMMIT();
    issue(1); CP_COMMIT();

    for (int t = 0; t < NKT; t++) {
        CP_WAIT1();
        __syncthreads();
        if (t + 2 < NKT) issue(t + 2);
        CP_COMMIT();

        const unsigned* As = (const unsigned*)smf + (t % 3) * STG_FLOATS;
        const unsigned* Bs = As + 4096;

#pragma unroll
        for (int kk = 0; kk < 4; kk++) {
            const int so = ((2 * kk) ^ g) << 2;   // chunk offset (floats)
            const int s1 = so ^ 4;
            unsigned af[2][4];
#pragma unroll
            for (int tt = 0; tt < 2; tt++) {
                int m0 = m_off + tt * 16 + g;
                af[tt][0] = As[m0 * 32 + so + kq];
                af[tt][1] = As[(m0 + 8) * 32 + so + kq];
                af[tt][2] = As[m0 * 32 + s1 + kq];
                af[tt][3] = As[(m0 + 8) * 32 + s1 + kq];
            }
            unsigned bf[8][2];
#pragma unroll
            for (int j = 0; j < 8; j++) {
                int n = n_off + j * 8 + g;
                bf[j][0] = Bs[n * 32 + so + kq];
                bf[j][1] = Bs[n * 32 + s1 + kq];
            }
#pragma unroll
            for (int tt = 0; tt < 2; tt++)
#pragma unroll
                for (int j = 0; j < 8; j++)
                    mma_tf32(acc[tt][j], af[tt], bf[j]);
        }
    }

    // epilogue: c0,c1 at (row, 2*kq+{0,1}); c2,c3 at (row+8, same cols)
#pragma unroll
    for (int t = 0; t < 2; t++) {
        int row = bm + m_off + t * 16 + g;
#pragma unroll
        for (int j = 0; j < 8; j++) {
            int col = bn + n_off + j * 8 + 2 * kq;
            float2 bb = *(const float2*)(bias + col);
            float2 v0 = { acc[t][j][0] + bb.x, acc[t][j][1] + bb.y };
            float2 v1 = { acc[t][j][2] + bb.x, acc[t][j][3] + bb.y };
            *(float2*)(C + (size_t)row * N + col)       = v0;
            *(float2*)(C + (size_t)(row + 8) * N + col) = v1;
        }
    }
}

// ---------------------------------------------------------------------------
// RoPE in place on q and k (first ROT=32 dims, half=16), positions = s.
// ---------------------------------------------------------------------------
__global__ void rope_kernel()
{
    int idx = blockIdx.x * blockDim.x + threadIdx.x;
    int d = idx & 15;
    int h = (idx >> 4) & (NH_ - 1);
    int s = (idx >> 8) & (S_ - 1);
    int b = idx >> 19;
    if (b >= B_) return;

    float inv = powf(10000.f, -((float)(2 * d) / 32.f));
    float ang = (float)s * inv;
    float c = cosf(ang);
    float sn = sinf(ang);

    float* base = g_qkv + ((size_t)(b * S_ + s)) * QKV3 + h * HEAD3;
    float x1 = base[d], x2 = base[d + 16];
    base[d]      = x1 * c - x2 * sn;
    base[d + 16] = x2 * c + x1 * sn;
    x1 = base[HS_ + d]; x2 = base[HS_ + d + 16];
    base[HS_ + d]      = x1 * c - x2 * sn;
    base[HS_ + d + 16] = x2 * c + x1 * sn;
}

// ---------------------------------------------------------------------------
// Flash attention, tf32 mma.sync. Q-tile 128 (8 warps x 16 rows), KV-tile 64.
// Epilogue stores tf32-rna-rounded values (feeds the dense GEMM's raw reads).
// ---------------------------------------------------------------------------
#define AQ_S 132
#define AV_S 136
#define AP_S 68
#define ATTN_SMEM ((128 * AQ_S + 64 * AQ_S + 64 * AV_S + 128 * AP_S) * 4)

__global__ __launch_bounds__(256)
void attn_kernel()
{
    extern __shared__ unsigned smu[];
    unsigned* Qs = smu;
    unsigned* Ks = Qs + 128 * AQ_S;
    unsigned* Vs = Ks + 64 * AQ_S;
    unsigned* Ps = Vs + 64 * AV_S;

    const int b = blockIdx.z, h = blockIdx.y, qt = blockIdx.x;
    const int tid  = threadIdx.x;
    const int wid  = tid >> 5;
    const int lane = tid & 31;
    const int g    = lane >> 2;
    const int kq   = lane & 3;
    const int wb   = wid * 16;
    const float scale = 0.08838834764831845f;

    const size_t qkvbase = (size_t)b * S_ * QKV3 + (size_t)h * HEAD3;

    for (int e = tid; e < 128 * 32; e += 256) {
        int row = e >> 5, c4 = e & 31;
        float4 v = *(const float4*)(g_qkv + qkvbase + (size_t)(qt * 128 + row) * QKV3 + c4 * 4);
        uint4 u = { f2tf(v.x), f2tf(v.y), f2tf(v.z), f2tf(v.w) };
        *(uint4*)&Qs[row * AQ_S + c4 * 4] = u;
    }

    float o[16][4];
#pragma unroll
    for (int n = 0; n < 16; n++)
#pragma unroll
        for (int e = 0; e < 4; e++) o[n][e] = 0.f;
    float m_i[2] = { -1e30f, -1e30f };
    float l_i[2] = { 0.f, 0.f };

    const int r0 = qt * 128 + wb + g;
    const int r1 = r0 + 8;
    const int ntiles = 2 * qt + 2;

    for (int kt = 0; kt < ntiles; kt++) {
        __syncthreads();
        for (int e = tid; e < 64 * 32; e += 256) {
            int row = e >> 5, c4 = e & 31;
            const float* gp = g_qkv + qkvbase + (size_t)(kt * 64 + row) * QKV3 + c4 * 4;
            float4 kv = *(const float4*)(gp + HS_);
            float4 vv = *(const float4*)(gp + 2 * HS_);
            uint4 ku = { f2tf(kv.x), f2tf(kv.y), f2tf(kv.z), f2tf(kv.w) };
            uint4 vu = { f2tf(vv.x), f2tf(vv.y), f2tf(vv.z), f2tf(vv.w) };
            *(uint4*)&Ks[row * AQ_S + c4 * 4] = ku;
            *(uint4*)&Vs[row * AV_S + c4 * 4] = vu;
        }
        __syncthreads();

        float sacc[8][4];
#pragma unroll
        for (int j = 0; j < 8; j++)
#pragma unroll
            for (int e = 0; e < 4; e++) sacc[j][e] = 0.f;

#pragma unroll
        for (int s = 0; s < 16; s++) {
            const int kb = s * 8 + kq;
            unsigned a[4];
            a[0] = Qs[(wb + g) * AQ_S + kb];
            a[1] = Qs[(wb + g + 8) * AQ_S + kb];
            a[2] = Qs[(wb + g) * AQ_S + kb + 4];
            a[3] = Qs[(wb + g + 8) * AQ_S + kb + 4];
#pragma unroll
            for (int j = 0; j < 8; j++) {
                unsigned bfr[2];
                bfr[0] = Ks[(j * 8 + g) * AQ_S + kb];
                bfr[1] = Ks[(j * 8 + g) * AQ_S + kb + 4];
                mma_tf32(sacc[j], a, bfr);
            }
        }

        const bool needmask = (kt * 64 + 63) > (qt * 128 + wb);
        if (needmask) {
#pragma unroll
            for (int j = 0; j < 8; j++) {
                int col = kt * 64 + j * 8 + 2 * kq;
#pragma unroll
                for (int e = 0; e < 2; e++) {
                    sacc[j][e]     = (col + e <= r0) ? sacc[j][e] * scale     : -1e30f;
                    sacc[j][2 + e] = (col + e <= r1) ? sacc[j][2 + e] * scale : -1e30f;
                }
            }
        } else {
#pragma unroll
            for (int j = 0; j < 8; j++)
#pragma unroll
                for (int e = 0; e < 4; e++) sacc[j][e] *= scale;
        }

#pragma unroll
        for (int rr = 0; rr < 2; rr++) {
            float tmax = -1e30f;
#pragma unroll
            for (int j = 0; j < 8; j++)
                tmax = fmaxf(tmax, fmaxf(sacc[j][rr * 2], sacc[j][rr * 2 + 1]));
            tmax = fmaxf(tmax, __shfl_xor_sync(0xffffffffu, tmax, 1));
            tmax = fmaxf(tmax, __shfl_xor_sync(0xffffffffu, tmax, 2));
            float m_new = fmaxf(m_i[rr], tmax);
            float alpha = __expf(m_i[rr] - m_new);

            float psum = 0.f;
#pragma unroll
            for (int j = 0; j < 8; j++) {
                float p0 = __expf(sacc[j][rr * 2]     - m_new);
                float p1 = __expf(sacc[j][rr * 2 + 1] - m_new);
                sacc[j][rr * 2]     = p0;
                sacc[j][rr * 2 + 1] = p1;
                psum += p0 + p1;
            }
            psum += __shfl_xor_sync(0xffffffffu, psum, 1);
            psum += __shfl_xor_sync(0xffffffffu, psum, 2);

            l_i[rr] = l_i[rr] * alpha + psum;
            m_i[rr] = m_new;
#pragma unroll
            for (int n = 0; n < 16; n++) {
                o[n][rr * 2]     *= alpha;
                o[n][rr * 2 + 1] *= alpha;
            }
        }

#pragma unroll
        for (int j = 0; j < 8; j++) {
            int cbase = j * 8 + 2 * kq;
            Ps[(wb + g) * AP_S + cbase]         = f2tf(sacc[j][0]);
            Ps[(wb + g) * AP_S + cbase + 1]     = f2tf(sacc[j][1]);
            Ps[(wb + g + 8) * AP_S + cbase]     = f2tf(sacc[j][2]);
            Ps[(wb + g + 8) * AP_S + cbase + 1] = f2tf(sacc[j][3]);
        }
        __syncwarp();

#pragma unroll
        for (int s = 0; s < 8; s++) {
            const int kb = s * 8 + kq;
            unsigned a[4];
            a[0] = Ps[(wb + g) * AP_S + kb];
            a[1] = Ps[(wb + g + 8) * AP_S + kb];
            a[2] = Ps[(wb + g) * AP_S + kb + 4];
            a[3] = Ps[(wb + g + 8) * AP_S + kb + 4];
#pragma unroll
            for (int n = 0; n < 16; n++) {
                unsigned bfr[2];
                bfr[0] = Vs[kb * AV_S + n * 8 + g];
                bfr[1] = Vs[(kb + 4) * AV_S + n * 8 + g];
                mma_tf32(o[n], a, bfr);
            }
        }
    }

    // epilogue: normalize, round to tf32 (dense GEMM reads raw bits), write
    const float invl0 = 1.f / l_i[0];
    const float invl1 = 1.f / l_i[1];
    float* out0 = g_attn + ((size_t)(b * S_) + r0) * HID_ + h * HS_;
    float* out1 = g_attn + ((size_t)(b * S_) + r1) * HID_ + h * HS_;
#pragma unroll
    for (int n = 0; n < 16; n++) {
        int col = n * 8 + 2 * kq;
        float2 v0 = { f2tf_f(o[n][0] * invl0), f2tf_f(o[n][1] * invl0) };
        float2 v1 = { f2tf_f(o[n][2] * invl1), f2tf_f(o[n][3] * invl1) };
        *(float2*)(out0 + col) = v0;
        *(float2*)(out1 + col) = v1;
    }
}

// ---------------------------------------------------------------------------
extern "C" void kernel_launch(void* const* d_in, const int* in_sizes, int n_in,
                              void* d_out, int out_size)
{
    const float* x      = (const float*)d_in[0];
    // d_in[1] position_ids (= arange, applied analytically)
    // d_in[2] attention_mask (= causal, applied analytically)
    const float* Wqkv   = (const float*)d_in[3];
    const float* bqkv   = (const float*)d_in[4];
    const float* Wdense = (const float*)d_in[5];
    const float* bdense = (const float*)d_in[6];
    float* out = (float*)d_out;

    float* qkv;   cudaGetSymbolAddress((void**)&qkv, g_qkv);
    float* attn;  cudaGetSymbolAddress((void**)&attn, g_attn);
    float* xr;    cudaGetSymbolAddress((void**)&xr, g_xr);
    float* wqkvT; cudaGetSymbolAddress((void**)&wqkvT, g_wqkvT);
    float* wdT;   cudaGetSymbolAddress((void**)&wdT, g_wdT);

    cudaFuncSetAttribute(gemm_mma, cudaFuncAttributeMaxDynamicSharedMemorySize, SM_GEMM_TOTAL);
    cudaFuncSetAttribute(attn_kernel, cudaFuncAttributeMaxDynamicSharedMemorySize, ATTN_SMEM);

    // 0) pre-pass: tf32-rna rounding + weight transposes
    {
        int n4 = (B_ * S_ * HID_) / 4;
        round_copy<<<(n4 + 255) / 256, 256>>>(x, xr, n4);
        dim3 blk(32, 8);
        transpose_round<<<dim3(QKV3 / 32, HID_ / 32), blk>>>(Wqkv, wqkvT, HID_, QKV3);
        transpose_round<<<dim3(HID_ / 32, HID_ / 32), blk>>>(Wdense, wdT, HID_, HID_);
    }

    // 1) QKV GEMM: [4096,2048] @ [2048,6144] + bias  (tf32 mma.sync + cp.async)
    {
        dim3 grid(QKV3 / 128, (B_ * S_) / 128);
        gemm_mma<<<grid, 256, SM_GEMM_TOTAL>>>(xr, wqkvT, bqkv, qkv, QKV3);
    }

    // 2) RoPE in place
    {
        int n = B_ * S_ * NH_ * 16;
        rope_kernel<<<n / 256, 256>>>();
    }

    // 3) Flash attention (tf32 mma.sync)
    {
        dim3 grid(S_ / 128, NH_, B_);
        attn_kernel<<<grid, 256, ATTN_SMEM>>>();
    }

    // 4) Dense GEMM: [4096,2048] @ [2048,2048] + bias -> d_out
    {
        dim3 grid(HID_ / 128, (B_ * S_) / 128);
        gemm_mma<<<grid, 256, SM_GEMM_TOTAL>>>(attn, wdT, bdense, out, HID_);
    }
}

// round 12
// speedup vs baseline: 3.7850x; 1.0205x over previous
#include <cuda_runtime.h>
#include <math.h>
#include <stdint.h>

#define B_    2
#define S_    2048
#define HID_  2048
#define NH_   16
#define HS_   128
#define QKV3  6144   // 3*HID
#define HEAD3 384    // 3*HS
#define K_    2048   // GEMM reduction dim (both GEMMs)

// Scratch (device globals — no allocation allowed)
__device__ float g_qkv[(size_t)B_ * S_ * QKV3];    // ~100 MB
__device__ float g_attn[(size_t)B_ * S_ * HID_];   // ~33 MB
__device__ float g_xr[(size_t)B_ * S_ * HID_];     // x, tf32-rounded
__device__ float g_wqkvT[(size_t)QKV3 * HID_];     // Wqkv^T, tf32-rounded
__device__ float g_wdT[(size_t)HID_ * HID_];       // Wdense^T, tf32-rounded

// ---------------------------------------------------------------------------
// helpers
// ---------------------------------------------------------------------------
__device__ __forceinline__ unsigned f2tf(float x) {
    unsigned r;
    asm("cvt.rna.tf32.f32 %0, %1;" : "=r"(r) : "f"(x));
    return r;
}
__device__ __forceinline__ float f2tf_f(float x) { return __uint_as_float(f2tf(x)); }

__device__ __forceinline__ void mma_tf32(float* c, const unsigned* a, const unsigned* b) {
    asm volatile(
        "mma.sync.aligned.m16n8k8.row.col.f32.tf32.tf32.f32 "
        "{%0,%1,%2,%3}, {%4,%5,%6,%7}, {%8,%9}, {%0,%1,%2,%3};"
        : "+f"(c[0]), "+f"(c[1]), "+f"(c[2]), "+f"(c[3])
        : "r"(a[0]), "r"(a[1]), "r"(a[2]), "r"(a[3]), "r"(b[0]), "r"(b[1]));
}

__device__ __forceinline__ uint32_t smem_u32(const void* p) {
    uint32_t a;
    asm("{ .reg .u64 t; cvta.to.shared.u64 t, %1; cvt.u32.u64 %0, t; }" : "=r"(a) : "l"(p));
    return a;
}

__device__ __forceinline__ void cp16(uint32_t dst, const void* src) {
    asm volatile("cp.async.ca.shared.global [%0], [%1], 16;" :: "r"(dst), "l"(src) : "memory");
}
#define CP_COMMIT() asm volatile("cp.async.commit_group;" ::: "memory")
#define CP_WAIT1()  asm volatile("cp.async.wait_group 1;" ::: "memory")

// ---------------------------------------------------------------------------
// Pre-pass kernels: tf32-rna rounding (and transpose for weights)
// ---------------------------------------------------------------------------
__global__ void round_copy(const float* __restrict__ src, float* __restrict__ dst, int n4)
{
    int i = blockIdx.x * blockDim.x + threadIdx.x;
    if (i >= n4) return;
    float4 v = ((const float4*)src)[i];
    float4 o = { f2tf_f(v.x), f2tf_f(v.y), f2tf_f(v.z), f2tf_f(v.w) };
    ((float4*)dst)[i] = o;
}

// src [rows][cols] -> dst [cols][rows], tf32-rna rounded
__global__ void transpose_round(const float* __restrict__ src, float* __restrict__ dst,
                                int rows, int cols)
{
    __shared__ float tile[32][33];
    int bx = blockIdx.x * 32;   // col base
    int by = blockIdx.y * 32;   // row base
    int tx = threadIdx.x, ty = threadIdx.y;
#pragma unroll
    for (int j = 0; j < 4; j++)
        tile[ty + j * 8][tx] = src[(size_t)(by + ty + j * 8) * cols + bx + tx];
    __syncthreads();
#pragma unroll
    for (int j = 0; j < 4; j++)
        dst[(size_t)(bx + ty + j * 8) * rows + by + tx] = f2tf_f(tile[tx][ty + j * 8]);
}

// ---------------------------------------------------------------------------
// tf32 mma.sync GEMM, cp.async 3-stage pipeline, tile 256x128x32.
// C[M,N] = A[M,K] @ Bt[N,K]^T + bias[N].  A, Bt pre-rounded to tf32-rna.
// 256 thr (8 warps in 4x2), warp tile 64x64 = 4 m16 x 8 n8 -> 32 LDS : 32 MMA
// per k8 step (ratio 1.0 vs 1.5 before => tensor pipe becomes the binding pipe).
// Smem: XOR-swizzled 128B rows, chunk c of row r at r*128 + ((c^(r&7))<<4).
// Stage = A(32KB)+B(16KB) = 48KB, x3 = 144KB. 1 CTA/SM.
// ---------------------------------------------------------------------------
#define STG_FLOATS 12288                     // floats per stage (A 8192 + B 4096)
#define SM_GEMM_TOTAL (3 * STG_FLOATS * 4)   // 147456

__global__ __launch_bounds__(256)
void gemm_mma(const float* __restrict__ A, const float* __restrict__ Bt,
              const float* __restrict__ bias, float* __restrict__ C, int N)
{
    extern __shared__ float smf[];
    const uint32_t sb = smem_u32(smf);

    const int tid  = threadIdx.x;
    const int wid  = tid >> 5;
    const int lane = tid & 31;
    const int g    = lane >> 2;      // 0..7
    const int kq   = lane & 3;       // 0..3

    const int bm = blockIdx.y * 256;
    const int bn = blockIdx.x * 128;
    const int m_off = (wid >> 1) * 64;   // 0,64,128,192
    const int n_off = (wid & 1) * 64;    // 0,64

    // loader: thread covers (row = idx>>3, chunk c = idx&7), idx = tid + i*256
    const int l_row = tid >> 3;          // 0..31 (+32*i)
    const int l_c   = tid & 7;

    float acc[4][8][4];
#pragma unroll
    for (int t = 0; t < 4; t++)
#pragma unroll
        for (int j = 0; j < 8; j++)
#pragma unroll
            for (int e = 0; e < 4; e++) acc[t][j][e] = 0.f;

    const int NKT = K_ / 32;   // 64

    auto issue = [&](int kt) {
        const uint32_t stg = sb + (uint32_t)(kt % 3) * (STG_FLOATS * 4);
#pragma unroll
        for (int i = 0; i < 8; i++) {           // A: 256 rows
            int row = l_row + i * 32;
            uint32_t soff = (uint32_t)(row * 128 + ((l_c ^ (row & 7)) << 4));
            cp16(stg + soff, A + (size_t)(bm + row) * K_ + kt * 32 + l_c * 4);
        }
#pragma unroll
        for (int i = 0; i < 4; i++) {           // B: 128 rows
            int row = l_row + i * 32;
            uint32_t soff = (uint32_t)(row * 128 + ((l_c ^ (row & 7)) << 4));
            cp16(stg + 32768u + soff, Bt + (size_t)(bn + row) * K_ + kt * 32 + l_c * 4);
        }
    };

    issue(0); CP_COMMIT();
    issue(1); CP_COMMIT();

    for (int t = 0; t < NKT; t++) {
        CP_WAIT1();
        __syncthreads();
        if (t + 2 < NKT) issue(t + 2);
        CP_COMMIT();

        const unsigned* As = (const unsigned*)smf + (t % 3) * STG_FLOATS;
        const unsigned* Bs = As + 8192;

#pragma unroll
        for (int kk = 0; kk < 4; kk++) {
            const int so = ((2 * kk) ^ g) << 2;   // chunk offset (floats)
            const int s1 = so ^ 4;

            unsigned bf[8][2];
#pragma unroll
            for (int j = 0; j < 8; j++) {
                int n = n_off + j * 8 + g;
                bf[j][0] = Bs[n * 32 + so + kq];
                bf[j][1] = Bs[n * 32 + s1 + kq];
            }
#pragma unroll
            for (int tt = 0; tt < 4; tt++) {
                int m0 = m_off + tt * 16 + g;
                unsigned af[4];
                af[0] = As[m0 * 32 + so + kq];
                af[1] = As[(m0 + 8) * 32 + so + kq];
                af[2] = As[m0 * 32 + s1 + kq];
                af[3] = As[(m0 + 8) * 32 + s1 + kq];
#pragma unroll
                for (int j = 0; j < 8; j++)
                    mma_tf32(acc[tt][j], af, bf[j]);
            }
        }
    }

    // epilogue: c0,c1 at (row, 2*kq+{0,1}); c2,c3 at (row+8, same cols)
#pragma unroll
    for (int t = 0; t < 4; t++) {
        int row = bm + m_off + t * 16 + g;
#pragma unroll
        for (int j = 0; j < 8; j++) {
            int col = bn + n_off + j * 8 + 2 * kq;
            float2 bb = *(const float2*)(bias + col);
            float2 v0 = { acc[t][j][0] + bb.x, acc[t][j][1] + bb.y };
            float2 v1 = { acc[t][j][2] + bb.x, acc[t][j][3] + bb.y };
            *(float2*)(C + (size_t)row * N + col)       = v0;
            *(float2*)(C + (size_t)(row + 8) * N + col) = v1;
        }
    }
}

// ---------------------------------------------------------------------------
// RoPE in place on q and k (first ROT=32 dims, half=16), positions = s.
// ---------------------------------------------------------------------------
__global__ void rope_kernel()
{
    int idx = blockIdx.x * blockDim.x + threadIdx.x;
    int d = idx & 15;
    int h = (idx >> 4) & (NH_ - 1);
    int s = (idx >> 8) & (S_ - 1);
    int b = idx >> 19;
    if (b >= B_) return;

    float inv = powf(10000.f, -((float)(2 * d) / 32.f));
    float ang = (float)s * inv;
    float c = cosf(ang);
    float sn = sinf(ang);

    float* base = g_qkv + ((size_t)(b * S_ + s)) * QKV3 + h * HEAD3;
    float x1 = base[d], x2 = base[d + 16];
    base[d]      = x1 * c - x2 * sn;
    base[d + 16] = x2 * c + x1 * sn;
    x1 = base[HS_ + d]; x2 = base[HS_ + d + 16];
    base[HS_ + d]      = x1 * c - x2 * sn;
    base[HS_ + d + 16] = x2 * c + x1 * sn;
}

// ---------------------------------------------------------------------------
// Flash attention, tf32 mma.sync. Q-tile 128 (8 warps x 16 rows), KV-tile 64.
// Epilogue stores tf32-rna-rounded values (feeds the dense GEMM's raw reads).
// ---------------------------------------------------------------------------
#define AQ_S 132
#define AV_S 136
#define AP_S 68
#define ATTN_SMEM ((128 * AQ_S + 64 * AQ_S + 64 * AV_S + 128 * AP_S) * 4)

__global__ __launch_bounds__(256)
void attn_kernel()
{
    extern __shared__ unsigned smu[];
    unsigned* Qs = smu;
    unsigned* Ks = Qs + 128 * AQ_S;
    unsigned* Vs = Ks + 64 * AQ_S;
    unsigned* Ps = Vs + 64 * AV_S;

    const int b = blockIdx.z, h = blockIdx.y, qt = blockIdx.x;
    const int tid  = threadIdx.x;
    const int wid  = tid >> 5;
    const int lane = tid & 31;
    const int g    = lane >> 2;
    const int kq   = lane & 3;
    const int wb   = wid * 16;
    const float scale = 0.08838834764831845f;

    const size_t qkvbase = (size_t)b * S_ * QKV3 + (size_t)h * HEAD3;

    for (int e = tid; e < 128 * 32; e += 256) {
        int row = e >> 5, c4 = e & 31;
        float4 v = *(const float4*)(g_qkv + qkvbase + (size_t)(qt * 128 + row) * QKV3 + c4 * 4);
        uint4 u = { f2tf(v.x), f2tf(v.y), f2tf(v.z), f2tf(v.w) };
        *(uint4*)&Qs[row * AQ_S + c4 * 4] = u;
    }

    float o[16][4];
#pragma unroll
    for (int n = 0; n < 16; n++)
#pragma unroll
        for (int e = 0; e < 4; e++) o[n][e] = 0.f;
    float m_i[2] = { -1e30f, -1e30f };
    float l_i[2] = { 0.f, 0.f };

    const int r0 = qt * 128 + wb + g;
    const int r1 = r0 + 8;
    const int ntiles = 2 * qt + 2;

    for (int kt = 0; kt < ntiles; kt++) {
        __syncthreads();
        for (int e = tid; e < 64 * 32; e += 256) {
            int row = e >> 5, c4 = e & 31;
            const float* gp = g_qkv + qkvbase + (size_t)(kt * 64 + row) * QKV3 + c4 * 4;
            float4 kv = *(const float4*)(gp + HS_);
            float4 vv = *(const float4*)(gp + 2 * HS_);
            uint4 ku = { f2tf(kv.x), f2tf(kv.y), f2tf(kv.z), f2tf(kv.w) };
            uint4 vu = { f2tf(vv.x), f2tf(vv.y), f2tf(vv.z), f2tf(vv.w) };
            *(uint4*)&Ks[row * AQ_S + c4 * 4] = ku;
            *(uint4*)&Vs[row * AV_S + c4 * 4] = vu;
        }
        __syncthreads();

        float sacc[8][4];
#pragma unroll
        for (int j = 0; j < 8; j++)
#pragma unroll
            for (int e = 0; e < 4; e++) sacc[j][e] = 0.f;

#pragma unroll
        for (int s = 0; s < 16; s++) {
            const int kb = s * 8 + kq;
            unsigned a[4];
            a[0] = Qs[(wb + g) * AQ_S + kb];
            a[1] = Qs[(wb + g + 8) * AQ_S + kb];
            a[2] = Qs[(wb + g) * AQ_S + kb + 4];
            a[3] = Qs[(wb + g + 8) * AQ_S + kb + 4];
#pragma unroll
            for (int j = 0; j < 8; j++) {
                unsigned bfr[2];
                bfr[0] = Ks[(j * 8 + g) * AQ_S + kb];
                bfr[1] = Ks[(j * 8 + g) * AQ_S + kb + 4];
                mma_tf32(sacc[j], a, bfr);
            }
        }

        const bool needmask = (kt * 64 + 63) > (qt * 128 + wb);
        if (needmask) {
#pragma unroll
            for (int j = 0; j < 8; j++) {
                int col = kt * 64 + j * 8 + 2 * kq;
#pragma unroll
                for (int e = 0; e < 2; e++) {
                    sacc[j][e]     = (col + e <= r0) ? sacc[j][e] * scale     : -1e30f;
                    sacc[j][2 + e] = (col + e <= r1) ? sacc[j][2 + e] * scale : -1e30f;
                }
            }
        } else {
#pragma unroll
            for (int j = 0; j < 8; j++)
#pragma unroll
                for (int e = 0; e < 4; e++) sacc[j][e] *= scale;
        }

#pragma unroll
        for (int rr = 0; rr < 2; rr++) {
            float tmax = -1e30f;
#pragma unroll
            for (int j = 0; j < 8; j++)
                tmax = fmaxf(tmax, fmaxf(sacc[j][rr * 2], sacc[j][rr * 2 + 1]));
            tmax = fmaxf(tmax, __shfl_xor_sync(0xffffffffu, tmax, 1));
            tmax = fmaxf(tmax, __shfl_xor_sync(0xffffffffu, tmax, 2));
            float m_new = fmaxf(m_i[rr], tmax);
            float alpha = __expf(m_i[rr] - m_new);

            float psum = 0.f;
#pragma unroll
            for (int j = 0; j < 8; j++) {
                float p0 = __expf(sacc[j][rr * 2]     - m_new);
                float p1 = __expf(sacc[j][rr * 2 + 1] - m_new);
                sacc[j][rr * 2]     = p0;
                sacc[j][rr * 2 + 1] = p1;
                psum += p0 + p1;
            }
            psum += __shfl_xor_sync(0xffffffffu, psum, 1);
            psum += __shfl_xor_sync(0xffffffffu, psum, 2);

            l_i[rr] = l_i[rr] * alpha + psum;
            m_i[rr] = m_new;
#pragma unroll
            for (int n = 0; n < 16; n++) {
                o[n][rr * 2]     *= alpha;
                o[n][rr * 2 + 1] *= alpha;
            }
        }

#pragma unroll
        for (int j = 0; j < 8; j++) {
            int cbase = j * 8 + 2 * kq;
            Ps[(wb + g) * AP_S + cbase]         = f2tf(sacc[j][0]);
            Ps[(wb + g) * AP_S + cbase + 1]     = f2tf(sacc[j][1]);
            Ps[(wb + g + 8) * AP_S + cbase]     = f2tf(sacc[j][2]);
            Ps[(wb + g + 8) * AP_S + cbase + 1] = f2tf(sacc[j][3]);
        }
        __syncwarp();

#pragma unroll
        for (int s = 0; s < 8; s++) {
            const int kb = s * 8 + kq;
            unsigned a[4];
            a[0] = Ps[(wb + g) * AP_S + kb];
            a[1] = Ps[(wb + g + 8) * AP_S + kb];
            a[2] = Ps[(wb + g) * AP_S + kb + 4];
            a[3] = Ps[(wb + g + 8) * AP_S + kb + 4];
#pragma unroll
            for (int n = 0; n < 16; n++) {
                unsigned bfr[2];
                bfr[0] = Vs[kb * AV_S + n * 8 + g];
                bfr[1] = Vs[(kb + 4) * AV_S + n * 8 + g];
                mma_tf32(o[n], a, bfr);
            }
        }
    }

    // epilogue: normalize, round to tf32 (dense GEMM reads raw bits), write
    const float invl0 = 1.f / l_i[0];
    const float invl1 = 1.f / l_i[1];
    float* out0 = g_attn + ((size_t)(b * S_) + r0) * HID_ + h * HS_;
    float* out1 = g_attn + ((size_t)(b * S_) + r1) * HID_ + h * HS_;
#pragma unroll
    for (int n = 0; n < 16; n++) {
        int col = n * 8 + 2 * kq;
        float2 v0 = { f2tf_f(o[n][0] * invl0), f2tf_f(o[n][1] * invl0) };
        float2 v1 = { f2tf_f(o[n][2] * invl1), f2tf_f(o[n][3] * invl1) };
        *(float2*)(out0 + col) = v0;
        *(float2*)(out1 + col) = v1;
    }
}

// ---------------------------------------------------------------------------
extern "C" void kernel_launch(void* const* d_in, const int* in_sizes, int n_in,
                              void* d_out, int out_size)
{
    const float* x      = (const float*)d_in[0];
    // d_in[1] position_ids (= arange, applied analytically)
    // d_in[2] attention_mask (= causal, applied analytically)
    const float* Wqkv   = (const float*)d_in[3];
    const float* bqkv   = (const float*)d_in[4];
    const float* Wdense = (const float*)d_in[5];
    const float* bdense = (const float*)d_in[6];
    float* out = (float*)d_out;

    float* qkv;   cudaGetSymbolAddress((void**)&qkv, g_qkv);
    float* attn;  cudaGetSymbolAddress((void**)&attn, g_attn);
    float* xr;    cudaGetSymbolAddress((void**)&xr, g_xr);
    float* wqkvT; cudaGetSymbolAddress((void**)&wqkvT, g_wqkvT);
    float* wdT;   cudaGetSymbolAddress((void**)&wdT, g_wdT);

    cudaFuncSetAttribute(gemm_mma, cudaFuncAttributeMaxDynamicSharedMemorySize, SM_GEMM_TOTAL);
    cudaFuncSetAttribute(attn_kernel, cudaFuncAttributeMaxDynamicSharedMemorySize, ATTN_SMEM);

    // 0) pre-pass: tf32-rna rounding + weight transposes
    {
        int n4 = (B_ * S_ * HID_) / 4;
        round_copy<<<(n4 + 255) / 256, 256>>>(x, xr, n4);
        dim3 blk(32, 8);
        transpose_round<<<dim3(QKV3 / 32, HID_ / 32), blk>>>(Wqkv, wqkvT, HID_, QKV3);
        transpose_round<<<dim3(HID_ / 32, HID_ / 32), blk>>>(Wdense, wdT, HID_, HID_);
    }

    // 1) QKV GEMM: [4096,2048] @ [2048,6144] + bias  (tf32 mma.sync + cp.async)
    {
        dim3 grid(QKV3 / 128, (B_ * S_) / 256);
        gemm_mma<<<grid, 256, SM_GEMM_TOTAL>>>(xr, wqkvT, bqkv, qkv, QKV3);
    }

    // 2) RoPE in place
    {
        int n = B_ * S_ * NH_ * 16;
        rope_kernel<<<n / 256, 256>>>();
    }

    // 3) Flash attention (tf32 mma.sync)
    {
        dim3 grid(S_ / 128, NH_, B_);
        attn_kernel<<<grid, 256, ATTN_SMEM>>>();
    }

    // 4) Dense GEMM: [4096,2048] @ [2048,2048] + bias -> d_out
    {
        dim3 grid(HID_ / 128, (B_ * S_) / 256);
        gemm_mma<<<grid, 256, SM_GEMM_TOTAL>>>(attn, wdT, bdense, out, HID_);
    }
}